// round 3
// baseline (speedup 1.0000x reference)
#include <cuda_runtime.h>
#include <cuda_bf16.h>

// Scratch (no allocations allowed -> device globals).
__device__ float g_M1[100 * 100];   // level-1 partials: 100 chunk matrices (10x10)
__device__ float g_c1[100 * 10];    // level-1 partial biases
__device__ float g_M3[100];         // final composed matrix M (row-major [out][in])
__device__ float g_c3[10];          // final composed bias
__device__ unsigned int g_ctr;      // CTA-completion counter (zero-init, self-resetting)

// ---------------------------------------------------------------------------
// fold_all: ONE kernel that composes 1000 affine maps (h -> h*W^T + b) into one.
//   Phase A: 100 CTAs each fold 10 consecutive layers -> g_M1/g_c1.
//   Phase B: last CTA (atomic counter) tree-reduces the 100 partials -> g_M3/g_c3.
// Combine rule (apply (M,c) then layer (Wn,bn)):  M' = Wn@M,  c' = Wn@c + bn.
// ---------------------------------------------------------------------------
__global__ void __launch_bounds__(512) fold_all(const float* __restrict__ Ws,
                                                const float* __restrict__ bs) {
    __shared__ float SH[11000];          // phase B: SM=SH[0..9999], SC=SH[10000..10999]
    __shared__ unsigned int is_last;

    const int b   = blockIdx.x;
    const int tid = threadIdx.x;

    // ---- Phase A: fold chunk b (layers [10b, 10b+10)) ----
    float* In  = SH;          // 10 x 100
    float* cIn = SH + 1000;   // 10 x 10
    float* M   = SH + 1100;   // 100
    float* cv  = SH + 1200;   // 10

    const float* mb = Ws + (size_t)b * 1000;
    const float* cb = bs + (size_t)b * 100;
    for (int idx = tid; idx < 1000; idx += 512) In[idx]  = mb[idx];
    for (int idx = tid; idx < 100;  idx += 512) cIn[idx] = cb[idx];
    __syncthreads();

    if (tid < 100) M[tid]  = In[tid];
    if (tid < 10)  cv[tid] = cIn[tid];
    __syncthreads();

    const int ei = (tid % 100) / 10;
    const int ej = tid % 10;

    #pragma unroll 1
    for (int l = 1; l < 10; ++l) {
        float nm = 0.f, nc = 0.f;
        const float* Wn = &In[l * 100];
        if (tid < 100) {
            #pragma unroll
            for (int k = 0; k < 10; ++k) nm += Wn[ei * 10 + k] * M[k * 10 + ej];
        }
        if (tid < 10) {
            nc = cIn[l * 10 + tid];
            #pragma unroll
            for (int k = 0; k < 10; ++k) nc += Wn[tid * 10 + k] * cv[k];
        }
        __syncthreads();
        if (tid < 100) M[tid]  = nm;
        if (tid < 10)  cv[tid] = nc;
        __syncthreads();
    }

    if (tid < 100) g_M1[b * 100 + tid] = M[tid];
    if (tid < 10)  g_c1[b * 10 + tid]  = cv[tid];

    // ---- Completion handshake ----
    __threadfence();
    __syncthreads();
    if (tid == 0) {
        unsigned int old = atomicAdd(&g_ctr, 1u);
        is_last = (old == (unsigned)(gridDim.x - 1)) ? 1u : 0u;
    }
    __syncthreads();
    if (!is_last) return;
    __threadfence();

    // ---- Phase B (last CTA only): reduce 100 partials -> 1 ----
    float* SM = SH;           // 100 matrices x 100
    float* SC = SH + 10000;   // 100 biases  x 10
    for (int idx = tid; idx < 10000; idx += 512) SM[idx] = g_M1[idx];
    for (int idx = tid; idx < 1000;  idx += 512) SC[idx] = g_c1[idx];
    __syncthreads();

    // Level 2: 10 chains of 10 chunks each. 5 groups of 100 threads; each group
    // folds 2 chains sequentially (18 steps, lockstep across groups).
    const int g = tid / 100;        // group 0..4 (tid < 500 active)
    const int e = tid % 100;
    const int i2 = e / 10, j2 = e % 10;
    const bool act = (tid < 500);

    #pragma unroll 1
    for (int s = 0; s < 18; ++s) {
        int d, l;
        if (s < 9) { d = 2 * g;     l = s + 1; }
        else       { d = 2 * g + 1; l = s - 8; }
        float nm = 0.f, nc = 0.f;
        if (act) {
            const float* W = &SM[(d * 10 + l) * 100];
            const float* A = &SM[(d * 10) * 100];        // acc slot for chain d
            #pragma unroll
            for (int k = 0; k < 10; ++k) nm += W[i2 * 10 + k] * A[k * 10 + j2];
            if (e < 10) {
                nc = SC[(d * 10 + l) * 10 + e];
                #pragma unroll
                for (int k = 0; k < 10; ++k) nc += W[e * 10 + k] * SC[d * 100 + k];
            }
        }
        __syncthreads();
        if (act) {
            SM[d * 1000 + e] = nm;
            if (e < 10) SC[d * 100 + e] = nc;
        }
        __syncthreads();
    }

    // Level 3: fold the 10 chain results (slots d*1000 / d*100) sequentially.
    #pragma unroll 1
    for (int d = 1; d < 10; ++d) {
        float nm = 0.f, nc = 0.f;
        const float* W = &SM[d * 1000];
        if (tid < 100) {
            #pragma unroll
            for (int k = 0; k < 10; ++k) nm += W[i2 * 10 + k] * SM[k * 10 + j2];
        }
        if (tid < 10) {
            nc = SC[d * 100 + tid];
            #pragma unroll
            for (int k = 0; k < 10; ++k) nc += W[tid * 10 + k] * SC[k];
        }
        __syncthreads();
        if (tid < 100) SM[tid] = nm;
        if (tid < 10)  SC[tid] = nc;
        __syncthreads();
    }

    if (tid < 100) g_M3[tid] = SM[tid];
    if (tid < 10)  g_c3[tid] = SC[tid];
    if (tid == 0)  g_ctr = 0;   // reset for next graph replay
}

// ---------------------------------------------------------------------------
// apply: out[r] = x[r] @ M^T + c.  One PAIR of rows (80B = 5 float4) per thread.
// M lives in shared (broadcast LDS) so regs stay ~64 -> 32+ warps/SM.
// ---------------------------------------------------------------------------
__global__ void __launch_bounds__(256, 4) apply_kernel(const float* __restrict__ x,
                                                       float* __restrict__ out,
                                                       long long pairs,
                                                       long long rows) {
    __shared__ float sm[100];
    __shared__ float sc[10];
    {
        const int t = threadIdx.x;
        if (t < 100) sm[t] = g_M3[t];
        if (t < 10)  sc[t] = g_c3[t];
    }
    __syncthreads();

    const long long p = (long long)blockIdx.x * blockDim.x + threadIdx.x;

    if (p < pairs) {
        const float4* xp = (const float4*)(x + p * 20);   // 80B, 16B-aligned
        float4 v0 = xp[0], v1 = xp[1], v2 = xp[2], v3 = xp[3], v4 = xp[4];

        float h0[10], h1[10];
        h0[0] = v0.x; h0[1] = v0.y; h0[2] = v0.z; h0[3] = v0.w;
        h0[4] = v1.x; h0[5] = v1.y; h0[6] = v1.z; h0[7] = v1.w;
        h0[8] = v2.x; h0[9] = v2.y;
        h1[0] = v2.z; h1[1] = v2.w;
        h1[2] = v3.x; h1[3] = v3.y; h1[4] = v3.z; h1[5] = v3.w;
        h1[6] = v4.x; h1[7] = v4.y; h1[8] = v4.z; h1[9] = v4.w;

        float o0[10], o1[10];
        #pragma unroll
        for (int j = 0; j < 10; ++j) {
            float a = sc[j], bsum = sc[j];
            #pragma unroll
            for (int k = 0; k < 10; ++k) {
                const float mv = sm[j * 10 + k];
                a    += h0[k] * mv;
                bsum += h1[k] * mv;
            }
            o0[j] = a;
            o1[j] = bsum;
        }

        float4* op = (float4*)(out + p * 20);
        float4 s0, s1, s2, s3, s4;
        s0.x = o0[0]; s0.y = o0[1]; s0.z = o0[2]; s0.w = o0[3];
        s1.x = o0[4]; s1.y = o0[5]; s1.z = o0[6]; s1.w = o0[7];
        s2.x = o0[8]; s2.y = o0[9]; s2.z = o1[0]; s2.w = o1[1];
        s3.x = o1[2]; s3.y = o1[3]; s3.z = o1[4]; s3.w = o1[5];
        s4.x = o1[6]; s4.y = o1[7]; s4.z = o1[8]; s4.w = o1[9];
        op[0] = s0; op[1] = s1; op[2] = s2; op[3] = s3; op[4] = s4;
    } else {
        // Odd-row tail (rows is even in this problem; kept for safety).
        const long long r = 2 * pairs + (p - pairs);
        if (r < rows) {
            const float* xr = x + r * 10;
            float h[10];
            #pragma unroll
            for (int k = 0; k < 10; ++k) h[k] = xr[k];
            float* orow = out + r * 10;
            #pragma unroll
            for (int j = 0; j < 10; ++j) {
                float a = sc[j];
                #pragma unroll
                for (int k = 0; k < 10; ++k) a += h[k] * sm[j * 10 + k];
                orow[j] = a;
            }
        }
    }
}

extern "C" void kernel_launch(void* const* d_in, const int* in_sizes, int n_in,
                              void* d_out, int out_size) {
    // Identify inputs by element count: x=BATCH*10, Ws=1000*100, bs=1000*10.
    const float* x  = nullptr;
    const float* Ws = nullptr;
    const float* bs = nullptr;
    long long x_elems = 0;
    for (int i = 0; i < n_in; ++i) {
        if (in_sizes[i] == 1000 * 100) {
            Ws = (const float*)d_in[i];
        } else if (in_sizes[i] == 1000 * 10) {
            bs = (const float*)d_in[i];
        } else {
            x = (const float*)d_in[i];
            x_elems = in_sizes[i];
        }
    }
    const long long rows  = x_elems / 10;
    const long long pairs = rows >> 1;
    const long long tail  = rows - 2 * pairs;
    const long long items = pairs + tail;

    // Single fold kernel: 100 CTAs fold chunks, last CTA reduces to g_M3/g_c3.
    fold_all<<<100, 512>>>(Ws, bs);

    // Streaming apply: one pair per thread, max warp-level MLP.
    const int blocks = (int)((items + 255) / 256);
    apply_kernel<<<blocks, 256>>>(x, (float*)d_out, pairs, rows);
}